// round 3
// baseline (speedup 1.0000x reference)
#include <cuda_runtime.h>
#include <cuda_bf16.h>
#include <cstdint>

// GraphConvLayer: y[dst] += W[type-1] @ xblk[src] + Bv[type-1] (broadcast over B)
// x:  [N*8, 16] f32  -> node block = 128 contiguous floats at x + src*128
// W:  [T, 8, 8] f32, Bv: [T, 8] f32
// out: [N*8, 16] f32 -> node block = 128 contiguous floats at out + dst*128

#define WARPS_PER_BLOCK 8
#define THREADS (WARPS_PER_BLOCK * 32)

__global__ void __launch_bounds__(THREADS)
gcl_edge_kernel(const float* __restrict__ x,
                const float* __restrict__ W,
                const float* __restrict__ Bv,
                const int*   __restrict__ src,
                const int*   __restrict__ dst,
                const int*   __restrict__ etype,
                float* __restrict__ out,
                int E, int nW, int nB)
{
    // per-warp x staging: 8 warps * 128 floats
    __shared__ float xs[WARPS_PER_BLOCK][128];
    __shared__ float Wsh[512];   // up to 8 types * 64
    __shared__ float Bsh[64];    // up to 8 types * 8

    // stage W and Bv once per block
    for (int i = threadIdx.x; i < nW; i += THREADS) Wsh[i] = W[i];
    for (int i = threadIdx.x; i < nB; i += THREADS) Bsh[i] = Bv[i];
    __syncthreads();

    const int lane = threadIdx.x & 31;
    const int wl   = threadIdx.x >> 5;
    const int e    = blockIdx.x * WARPS_PER_BLOCK + wl;
    if (e >= E) return;

    const int s = src[e];
    const int d = dst[e];
    const int t = etype[e] - 1;

    // cooperative load of src node block (512B contiguous)
    const float4* xb = reinterpret_cast<const float4*>(x + (size_t)s * 128);
    reinterpret_cast<float4*>(xs[wl])[lane] = xb[lane];
    __syncwarp();

    // lane -> (out-row o, col-group cg): lane = o*4 + cg, cg covers cols [cg*4, cg*4+4)
    const int o  = lane >> 2;
    const int cg = lane & 3;

    const float* Wo = Wsh + t * 64 + o * 8;
    const float  b  = Bsh[t * 8 + o];

    float a0 = b, a1 = b, a2 = b, a3 = b;
    #pragma unroll
    for (int i = 0; i < 8; i++) {
        const float w = Wo[i];
        const float* xr = &xs[wl][i * 16 + cg * 4];
        a0 += w * xr[0];
        a1 += w * xr[1];
        a2 += w * xr[2];
        a3 += w * xr[3];
    }

    float* op = out + (size_t)d * 128 + o * 16 + cg * 4;
    asm volatile("red.global.add.v4.f32 [%0], {%1, %2, %3, %4};"
                 :: "l"(op), "f"(a0), "f"(a1), "f"(a2), "f"(a3)
                 : "memory");
}

extern "C" void kernel_launch(void* const* d_in, const int* in_sizes, int n_in,
                              void* d_out, int out_size)
{
    const float* x   = (const float*)d_in[0];
    const float* W   = (const float*)d_in[1];
    const float* Bv  = (const float*)d_in[2];
    const int*   src = (const int*)  d_in[3];
    const int*   dst = (const int*)  d_in[4];
    const int*   et  = (const int*)  d_in[5];
    float*       out = (float*)d_out;

    const int E  = in_sizes[3];
    const int nW = in_sizes[1];
    const int nB = in_sizes[2];

    cudaMemsetAsync(out, 0, (size_t)out_size * sizeof(float));

    const int blocks = (E + WARPS_PER_BLOCK - 1) / WARPS_PER_BLOCK;
    gcl_edge_kernel<<<blocks, THREADS>>>(x, W, Bv, src, dst, et, out, E, nW, nB);
}

// round 4
// speedup vs baseline: 2.7047x; 2.7047x over previous
#include <cuda_runtime.h>
#include <cuda_bf16.h>
#include <cstdint>

// GraphConvLayer via CSR-by-dst + per-type aggregation:
//   agg_t[n] = sum_{e: dst=n, type=t} x[src_e]   (pure gather-add, registers)
//   y[n]     = sum_t W_t @ agg_t[n] + cnt_t[n] * Bv_t   (once per node)
//
// x block = 128 contiguous floats at x + node*128 ([8 rows][16 cols]).

#define MAXE 1700000
#define MAXN 50001
#define NTYPES 5

__device__ int g_cnt[MAXN];
__device__ int g_off[MAXN + 1];
__device__ int g_cur[MAXN];
__device__ int g_packed[MAXE];

// ---------------- CSR build ----------------

__global__ void hist_kernel(const int* __restrict__ dst, int E) {
    int e = blockIdx.x * blockDim.x + threadIdx.x;
    if (e < E) atomicAdd(&g_cnt[dst[e]], 1);
}

__global__ void __launch_bounds__(1024) scan_kernel(int N) {
    __shared__ int wtot[32];
    __shared__ int run_sh;
    const int tid = threadIdx.x, lane = tid & 31, w = tid >> 5;
    if (tid == 0) run_sh = 0;
    __syncthreads();
    for (int base = 0; base < N; base += 1024) {
        int i = base + tid;
        int v = (i < N) ? g_cnt[i] : 0;
        int xv = v;
        #pragma unroll
        for (int s = 1; s < 32; s <<= 1) {
            int y = __shfl_up_sync(0xffffffffu, xv, s);
            if (lane >= s) xv += y;
        }
        if (lane == 31) wtot[w] = xv;
        __syncthreads();
        if (w == 0) {
            int y = wtot[lane];
            #pragma unroll
            for (int s = 1; s < 32; s <<= 1) {
                int z = __shfl_up_sync(0xffffffffu, y, s);
                if (lane >= s) y += z;
            }
            wtot[lane] = y;
        }
        __syncthreads();
        const int excl = xv - v + ((w > 0) ? wtot[w - 1] : 0);
        const int r = run_sh;
        if (i < N) { g_off[i] = r + excl; g_cur[i] = r + excl; }
        const int btot = wtot[31];
        __syncthreads();
        if (tid == 0) run_sh = r + btot;
        __syncthreads();
    }
    if (threadIdx.x == 0) g_off[N] = run_sh;
}

__global__ void scatter_kernel(const int* __restrict__ src,
                               const int* __restrict__ dst,
                               const int* __restrict__ et, int E) {
    int e = blockIdx.x * blockDim.x + threadIdx.x;
    if (e < E) {
        int d = dst[e];
        int p = atomicAdd(&g_cur[d], 1);
        g_packed[p] = src[e] | ((et[e] - 1) << 17);
    }
}

// ---------------- main kernel: warp per node ----------------

__global__ void __launch_bounds__(256)
gcl_main(const float* __restrict__ x,
         const float* __restrict__ W,
         const float* __restrict__ Bv,
         float* __restrict__ out, int N) {
    __shared__ float Wsh[NTYPES][8][9];   // padded to kill bank conflicts
    __shared__ float Bsh[NTYPES][8];
    __shared__ float aggS[8][NTYPES * 128];  // per-warp transpose buffer (20KB)

    const int tid = threadIdx.x;
    for (int i = tid; i < NTYPES * 64; i += 256) {
        int t = i >> 6, rem = i & 63;
        Wsh[t][rem >> 3][rem & 7] = W[i];
    }
    for (int i = tid; i < NTYPES * 8; i += 256) Bsh[i >> 3][i & 7] = Bv[i];
    __syncthreads();

    const int lane = tid & 31, wl = tid >> 5;
    const int n = blockIdx.x * 8 + wl;
    if (n >= N) return;

    const int beg = g_off[n], end = g_off[n + 1];

    unsigned long long a01[NTYPES], a23[NTYPES];
    int cnt[NTYPES];
    #pragma unroll
    for (int t = 0; t < NTYPES; t++) { a01[t] = 0ull; a23[t] = 0ull; cnt[t] = 0; }

    for (int base = beg; base < end; base += 32) {
        const int j = base + lane;
        const int pk = (j < end) ? g_packed[j] : 0;
        int m = end - base; if (m > 32) m = 32;

        // software pipeline: prefetch next edge's x chunk while accumulating
        int pk0 = __shfl_sync(0xffffffffu, pk, 0);
        int tnext = pk0 >> 17;
        ulonglong2 vnext =
            ((const ulonglong2*)(x + (size_t)(pk0 & 0x1FFFF) * 128))[lane];

        for (int k = 0; k < m; k++) {
            ulonglong2 vc = vnext;
            const int tc = tnext;
            if (k + 1 < m) {
                int pkn = __shfl_sync(0xffffffffu, pk, k + 1);
                tnext = pkn >> 17;
                vnext = ((const ulonglong2*)(x + (size_t)(pkn & 0x1FFFF) * 128))[lane];
            }
            // predicated per-type accumulate: 2x f32x2 add + count, type is warp-uniform
            #pragma unroll
            for (int tt = 0; tt < NTYPES; tt++) {
                asm volatile(
                    "{\n\t.reg .pred p;\n\t"
                    "setp.eq.s32 p, %5, %6;\n\t"
                    "@p add.rn.f32x2 %0, %0, %3;\n\t"
                    "@p add.rn.f32x2 %1, %1, %4;\n\t"
                    "@p add.s32 %2, %2, 1;\n\t}"
                    : "+l"(a01[tt]), "+l"(a23[tt]), "+r"(cnt[tt])
                    : "l"(vc.x), "l"(vc.y), "r"(tc), "r"(tt));
            }
        }
    }

    // transpose agg through shared, then 8x8 transform + bias, single STG
    float* myAgg = aggS[wl];
    const int r = lane >> 2, cg = lane & 3;
    #pragma unroll
    for (int tt = 0; tt < NTYPES; tt++) {
        ulonglong2 u; u.x = a01[tt]; u.y = a23[tt];
        *(ulonglong2*)(myAgg + tt * 128 + r * 16 + cg * 4) = u;
    }
    __syncwarp();

    const int o = lane >> 2;
    float ax = 0.f, ay = 0.f, az = 0.f, aw = 0.f, bias = 0.f;
    #pragma unroll
    for (int tt = 0; tt < NTYPES; tt++) {
        const float* ag = myAgg + tt * 128 + cg * 4;
        #pragma unroll
        for (int i = 0; i < 8; i++) {
            const float wv = Wsh[tt][o][i];
            const float4 a = *(const float4*)(ag + i * 16);
            ax += wv * a.x; ay += wv * a.y; az += wv * a.z; aw += wv * a.w;
        }
        bias += (float)cnt[tt] * Bsh[tt][o];
    }
    float4 res = { ax + bias, ay + bias, az + bias, aw + bias };
    *(float4*)(out + (size_t)n * 128 + o * 16 + cg * 4) = res;
}

// ---------------- launch ----------------

extern "C" void kernel_launch(void* const* d_in, const int* in_sizes, int n_in,
                              void* d_out, int out_size)
{
    const float* x   = (const float*)d_in[0];
    const float* W   = (const float*)d_in[1];
    const float* Bv  = (const float*)d_in[2];
    const int*   src = (const int*)  d_in[3];
    const int*   dst = (const int*)  d_in[4];
    const int*   et  = (const int*)  d_in[5];
    float*       out = (float*)d_out;

    const int E = in_sizes[3];
    const int N = in_sizes[0] / 128;   // x is [N*8, 16] f32

    void* cnt_ptr = nullptr;
    cudaGetSymbolAddress(&cnt_ptr, g_cnt);
    cudaMemsetAsync(cnt_ptr, 0, (size_t)N * sizeof(int));

    const int tb = 256;
    hist_kernel<<<(E + tb - 1) / tb, tb>>>(dst, E);
    scan_kernel<<<1, 1024>>>(N);
    scatter_kernel<<<(E + tb - 1) / tb, tb>>>(src, dst, et, E);
    gcl_main<<<(N + 7) / 8, 256>>>(x, W, Bv, out, N);
}

// round 8
// speedup vs baseline: 4.5355x; 1.6769x over previous
#include <cuda_runtime.h>
#include <cuda_bf16.h>
#include <cstdint>

// GraphConvLayer via CSR keyed by (dst*5 + type):
//   edges of each type contiguous per node -> single running accumulator,
//   folded through W[t] at type boundaries (<=5 folds/node).
//   bias = sum_t seglen(n,t) * Bv[t]  (counts free from offsets)

#define NTYPES 5
#define MAXE   1700000
#define MAXB   250001      // N*NTYPES bins (N<=50000)
#define SCAN_BS 1024

__device__ int g_cnt[MAXB];
__device__ int g_off[MAXB + 1];
__device__ int g_cur[MAXB];
__device__ int g_packed[MAXE];
__device__ int g_bsum[512];
__device__ int g_bsumx[512];

// ---------------- CSR build ----------------

__global__ void hist_kernel(const int* __restrict__ dst,
                            const int* __restrict__ et, int E) {
    int e = blockIdx.x * blockDim.x + threadIdx.x;
    if (e < E) atomicAdd(&g_cnt[dst[e] * NTYPES + (et[e] - 1)], 1);
}

__device__ __forceinline__ int block_exscan_1024(int v, int* wtot) {
    const int lane = threadIdx.x & 31, w = threadIdx.x >> 5;
    int xv = v;
    #pragma unroll
    for (int s = 1; s < 32; s <<= 1) {
        int y = __shfl_up_sync(0xffffffffu, xv, s);
        if (lane >= s) xv += y;
    }
    if (lane == 31) wtot[w] = xv;
    __syncthreads();
    if (w == 0) {
        int y = (lane < 32) ? wtot[lane] : 0;
        #pragma unroll
        for (int s = 1; s < 32; s <<= 1) {
            int z = __shfl_up_sync(0xffffffffu, y, s);
            if (lane >= s) y += z;
        }
        wtot[lane] = y;
    }
    __syncthreads();
    return xv - v + ((w > 0) ? wtot[w - 1] : 0);   // exclusive within block
}

__global__ void __launch_bounds__(SCAN_BS) scan_pass1(int B) {
    __shared__ int wtot[32];
    int i = blockIdx.x * SCAN_BS + threadIdx.x;
    int v = (i < B) ? g_cnt[i] : 0;
    int excl = block_exscan_1024(v, wtot);
    if (threadIdx.x == SCAN_BS - 1) g_bsum[blockIdx.x] = excl + v;
}

__global__ void __launch_bounds__(SCAN_BS) scan_pass2(int nblk, int B, int E) {
    __shared__ int wtot[32];
    int v = (threadIdx.x < nblk) ? g_bsum[threadIdx.x] : 0;
    int excl = block_exscan_1024(v, wtot);
    if (threadIdx.x < nblk) g_bsumx[threadIdx.x] = excl;
    if (threadIdx.x == 0) g_off[B] = E;
}

__global__ void __launch_bounds__(SCAN_BS) scan_pass3(int B) {
    __shared__ int wtot[32];
    int i = blockIdx.x * SCAN_BS + threadIdx.x;
    int v = (i < B) ? g_cnt[i] : 0;
    int excl = block_exscan_1024(v, wtot) + g_bsumx[blockIdx.x];
    if (i < B) { g_off[i] = excl; g_cur[i] = excl; }
}

__global__ void scatter_kernel(const int* __restrict__ src,
                               const int* __restrict__ dst,
                               const int* __restrict__ et, int E) {
    int e = blockIdx.x * blockDim.x + threadIdx.x;
    if (e < E) {
        int bin = dst[e] * NTYPES + (et[e] - 1);
        int p = atomicAdd(&g_cur[bin], 1);
        g_packed[p] = src[e];
    }
}

// ---------------- main kernel: warp per node ----------------

__global__ void __launch_bounds__(256)
gcl_main(const float* __restrict__ x,
         const float* __restrict__ W,
         const float* __restrict__ Bv,
         float* __restrict__ out, int N)
{
    __shared__ float Wsh[NTYPES][8][8];
    __shared__ float Bsh[NTYPES][8];
    __shared__ float aggS[8][8][16];     // [warp][row][col] 4KB

    const int tid = threadIdx.x;
    for (int i = tid; i < NTYPES * 64; i += 256) {
        int t = i >> 6, rem = i & 63;
        Wsh[t][rem >> 3][rem & 7] = W[i];
    }
    for (int i = tid; i < NTYPES * 8; i += 256) Bsh[i >> 3][i & 7] = Bv[i];
    __syncthreads();

    const int lane = tid & 31, wl = tid >> 5;
    const int n = blockIdx.x * 8 + wl;
    if (n >= N) return;

    // type boundaries: bnd[k] = g_off[n*5+k], k = 0..5, one per lane, shfl on demand
    const int myBnd = g_off[n * NTYPES + ((lane < NTYPES + 1) ? lane : NTYPES)];
    const int beg = __shfl_sync(0xffffffffu, myBnd, 0);
    const int end = __shfl_sync(0xffffffffu, myBnd, NTYPES);

    const int o  = lane >> 2;     // out row
    const int cg = lane & 3;      // col group (4 cols)
    const int r  = lane >> 2;     // in row for acc layout (lane holds x[r][cg*4..+4))

    unsigned long long a01 = 0ull, a23 = 0ull;   // running sum, 4 floats as 2x f32x2
    float ax = 0.f, ay = 0.f, az = 0.f, aw = 0.f;

    int tcur = 0;
    int nextB = __shfl_sync(0xffffffffu, myBnd, 1);

    for (int base = beg; base < end; base += 32) {
        const int j32 = base + lane;
        const int pk = (j32 < end) ? g_packed[j32] : 0;
        int m = end - base; if (m > 32) m = 32;

        int s0 = __shfl_sync(0xffffffffu, pk, 0);
        ulonglong2 vnext = ((const ulonglong2*)(x + (size_t)s0 * 128))[lane];

        for (int k = 0; k < m; k++) {
            ulonglong2 vc = vnext;
            if (k + 1 < m) {
                int sn = __shfl_sync(0xffffffffu, pk, k + 1);
                vnext = ((const ulonglong2*)(x + (size_t)sn * 128))[lane];
            }
            const int j = base + k;
            // warp-uniform type-boundary folds
            while (j >= nextB) {
                // fold acc through W[tcur] via shared transpose
                ulonglong2 u; u.x = a01; u.y = a23;
                *(ulonglong2*)(&aggS[wl][r][cg * 4]) = u;
                __syncwarp();
                #pragma unroll
                for (int i = 0; i < 8; i++) {
                    const float wv = Wsh[tcur][o][i];
                    const float4 a = *(const float4*)(&aggS[wl][i][cg * 4]);
                    ax += wv * a.x; ay += wv * a.y; az += wv * a.z; aw += wv * a.w;
                }
                __syncwarp();
                a01 = 0ull; a23 = 0ull;
                tcur++;
                nextB = __shfl_sync(0xffffffffu, myBnd,
                                    (tcur < NTYPES) ? (tcur + 1) : NTYPES);
            }
            asm volatile("add.rn.f32x2 %0, %0, %2;\n\t"
                         "add.rn.f32x2 %1, %1, %3;"
                         : "+l"(a01), "+l"(a23)
                         : "l"(vc.x), "l"(vc.y));
        }
    }

    // final fold for the last non-empty segment
    {
        ulonglong2 u; u.x = a01; u.y = a23;
        *(ulonglong2*)(&aggS[wl][r][cg * 4]) = u;
        __syncwarp();
        #pragma unroll
        for (int i = 0; i < 8; i++) {
            const float wv = Wsh[tcur][o][i];
            const float4 a = *(const float4*)(&aggS[wl][i][cg * 4]);
            ax += wv * a.x; ay += wv * a.y; az += wv * a.z; aw += wv * a.w;
        }
    }

    // bias from segment lengths
    float bias = 0.f;
    #pragma unroll
    for (int t = 0; t < NTYPES; t++) {
        int lo = __shfl_sync(0xffffffffu, myBnd, t);
        int hi = __shfl_sync(0xffffffffu, myBnd, t + 1);
        bias += (float)(hi - lo) * Bsh[t][o];
    }

    float4 res = { ax + bias, ay + bias, az + bias, aw + bias };
    *(float4*)(out + (size_t)n * 128 + o * 16 + cg * 4) = res;
}

// ---------------- launch ----------------

extern "C" void kernel_launch(void* const* d_in, const int* in_sizes, int n_in,
                              void* d_out, int out_size)
{
    const float* x   = (const float*)d_in[0];
    const float* W   = (const float*)d_in[1];
    const float* Bv  = (const float*)d_in[2];
    const int*   src = (const int*)  d_in[3];
    const int*   dst = (const int*)  d_in[4];
    const int*   et  = (const int*)  d_in[5];
    float*       out = (float*)d_out;

    const int E = in_sizes[3];
    const int N = in_sizes[0] / 128;
    const int B = N * NTYPES;

    void* cnt_ptr = nullptr;
    cudaGetSymbolAddress(&cnt_ptr, g_cnt);
    cudaMemsetAsync(cnt_ptr, 0, (size_t)B * sizeof(int));

    const int tb = 256;
    hist_kernel<<<(E + tb - 1) / tb, tb>>>(dst, et, E);

    const int nblk = (B + SCAN_BS - 1) / SCAN_BS;
    scan_pass1<<<nblk, SCAN_BS>>>(B);
    scan_pass2<<<1, SCAN_BS>>>(nblk, B, E);
    scan_pass3<<<nblk, SCAN_BS>>>(B);

    scatter_kernel<<<(E + tb - 1) / tb, tb>>>(src, dst, et, E);
    gcl_main<<<(N + 7) / 8, 256>>>(x, W, Bv, out, N);
}

// round 9
// speedup vs baseline: 4.6849x; 1.0329x over previous
#include <cuda_runtime.h>
#include <cuda_bf16.h>
#include <cstdint>

// GraphConvLayer via CSR keyed by (dst*5 + type), type-contiguous segments,
// fold-at-boundary. This round: depth-4 gather pipeline in main, atomic-free
// scatter (rank captured during histogram).

#define NTYPES 5
#define MAXE   1700000
#define MAXB   250001
#define SCAN_BS 1024

__device__ int g_cnt[MAXB];
__device__ int g_off[MAXB + 1];
__device__ int g_rank[MAXE];
__device__ int g_bin[MAXE];
__device__ int g_packed[MAXE];
__device__ int g_bsum[512];
__device__ int g_bsumx[512];

// ---------------- CSR build ----------------

__global__ void hist_kernel(const int* __restrict__ dst,
                            const int* __restrict__ et, int E) {
    int e = blockIdx.x * blockDim.x + threadIdx.x;
    if (e < E) {
        int bin = dst[e] * NTYPES + (et[e] - 1);
        g_bin[e]  = bin;
        g_rank[e] = atomicAdd(&g_cnt[bin], 1);
    }
}

__device__ __forceinline__ int block_exscan_1024(int v, int* wtot) {
    const int lane = threadIdx.x & 31, w = threadIdx.x >> 5;
    int xv = v;
    #pragma unroll
    for (int s = 1; s < 32; s <<= 1) {
        int y = __shfl_up_sync(0xffffffffu, xv, s);
        if (lane >= s) xv += y;
    }
    if (lane == 31) wtot[w] = xv;
    __syncthreads();
    if (w == 0) {
        int y = wtot[lane];
        #pragma unroll
        for (int s = 1; s < 32; s <<= 1) {
            int z = __shfl_up_sync(0xffffffffu, y, s);
            if (lane >= s) y += z;
        }
        wtot[lane] = y;
    }
    __syncthreads();
    return xv - v + ((w > 0) ? wtot[w - 1] : 0);
}

__global__ void __launch_bounds__(SCAN_BS) scan_pass1(int B) {
    __shared__ int wtot[32];
    int i = blockIdx.x * SCAN_BS + threadIdx.x;
    int v = (i < B) ? g_cnt[i] : 0;
    int excl = block_exscan_1024(v, wtot);
    if (threadIdx.x == SCAN_BS - 1) g_bsum[blockIdx.x] = excl + v;
}

__global__ void __launch_bounds__(SCAN_BS) scan_pass2(int nblk, int B, int E) {
    __shared__ int wtot[32];
    int v = (threadIdx.x < nblk) ? g_bsum[threadIdx.x] : 0;
    int excl = block_exscan_1024(v, wtot);
    if (threadIdx.x < nblk) g_bsumx[threadIdx.x] = excl;
    if (threadIdx.x == 0) g_off[B] = E;
}

__global__ void __launch_bounds__(SCAN_BS) scan_pass3(int B) {
    __shared__ int wtot[32];
    int i = blockIdx.x * SCAN_BS + threadIdx.x;
    int v = (i < B) ? g_cnt[i] : 0;
    int excl = block_exscan_1024(v, wtot) + g_bsumx[blockIdx.x];
    if (i < B) g_off[i] = excl;
}

// atomic-free: position = base offset of bin + rank captured during histogram
__global__ void scatter_kernel(const int* __restrict__ src, int E) {
    int e = blockIdx.x * blockDim.x + threadIdx.x;
    if (e < E) {
        int p = g_off[g_bin[e]] + g_rank[e];
        g_packed[p] = src[e];
    }
}

// ---------------- main kernel: warp per node, MLP-4 gather ----------------

__global__ void __launch_bounds__(256)
gcl_main(const float* __restrict__ x,
         const float* __restrict__ W,
         const float* __restrict__ Bv,
         float* __restrict__ out, int N)
{
    __shared__ float Wsh[NTYPES][8][8];
    __shared__ float Bsh[NTYPES][8];
    __shared__ float aggS[8][8][16];

    const int tid = threadIdx.x;
    for (int i = tid; i < NTYPES * 64; i += 256) {
        int t = i >> 6, rem = i & 63;
        Wsh[t][rem >> 3][rem & 7] = W[i];
    }
    for (int i = tid; i < NTYPES * 8; i += 256) Bsh[i >> 3][i & 7] = Bv[i];
    __syncthreads();

    const int lane = tid & 31, wl = tid >> 5;
    const int n = blockIdx.x * 8 + wl;
    if (n >= N) return;

    const int myBnd = g_off[n * NTYPES + ((lane < NTYPES + 1) ? lane : NTYPES)];
    const int beg = __shfl_sync(0xffffffffu, myBnd, 0);
    const int end = __shfl_sync(0xffffffffu, myBnd, NTYPES);

    const int o  = lane >> 2;
    const int cg = lane & 3;

    unsigned long long a01 = 0ull, a23 = 0ull;
    float ax = 0.f, ay = 0.f, az = 0.f, aw = 0.f;

    int tcur = 0;
    int nextB = __shfl_sync(0xffffffffu, myBnd, 1);

    const ulonglong2* __restrict__ xq = (const ulonglong2*)x;

    for (int base = beg; base < end; base += 32) {
        const int j32 = base + lane;
        const int pk = (j32 < end) ? g_packed[j32] : 0;
        int m = end - base; if (m > 32) m = 32;

        // prefetch group 0 (4 independent loads -> MLP 4)
        ulonglong2 v0, v1, v2, v3;
        {
            int s0 = __shfl_sync(0xffffffffu, pk, 0);
            int s1 = __shfl_sync(0xffffffffu, pk, (1 < m) ? 1 : 0);
            int s2 = __shfl_sync(0xffffffffu, pk, (2 < m) ? 2 : 0);
            int s3 = __shfl_sync(0xffffffffu, pk, (3 < m) ? 3 : 0);
            v0 = xq[(size_t)s0 * 32 + lane];
            v1 = xq[(size_t)s1 * 32 + lane];
            v2 = xq[(size_t)s2 * 32 + lane];
            v3 = xq[(size_t)s3 * 32 + lane];
        }

        for (int k0 = 0; k0 < m; k0 += 4) {
            ulonglong2 c0 = v0, c1 = v1, c2 = v2, c3 = v3;
            // issue next group's loads before consuming current group
            if (k0 + 4 < m) {
                int k4 = k0 + 4;
                int s0 = __shfl_sync(0xffffffffu, pk, k4);
                int s1 = __shfl_sync(0xffffffffu, pk, (k4 + 1 < m) ? k4 + 1 : k4);
                int s2 = __shfl_sync(0xffffffffu, pk, (k4 + 2 < m) ? k4 + 2 : k4);
                int s3 = __shfl_sync(0xffffffffu, pk, (k4 + 3 < m) ? k4 + 3 : k4);
                v0 = xq[(size_t)s0 * 32 + lane];
                v1 = xq[(size_t)s1 * 32 + lane];
                v2 = xq[(size_t)s2 * 32 + lane];
                v3 = xq[(size_t)s3 * 32 + lane];
            }

            #pragma unroll
            for (int q = 0; q < 4; q++) {
                const int k = k0 + q;
                if (k < m) {
                    const int j = base + k;
                    while (j >= nextB) {   // warp-uniform type-boundary fold
                        ulonglong2 u; u.x = a01; u.y = a23;
                        *(ulonglong2*)(&aggS[wl][o][cg * 4]) = u;
                        __syncwarp();
                        #pragma unroll
                        for (int i = 0; i < 8; i++) {
                            const float wv = Wsh[tcur][o][i];
                            const float4 a = *(const float4*)(&aggS[wl][i][cg * 4]);
                            ax += wv * a.x; ay += wv * a.y;
                            az += wv * a.z; aw += wv * a.w;
                        }
                        __syncwarp();
                        a01 = 0ull; a23 = 0ull;
                        tcur++;
                        nextB = __shfl_sync(0xffffffffu, myBnd,
                                            (tcur < NTYPES) ? (tcur + 1) : NTYPES);
                    }
                    const ulonglong2 vc = (q == 0) ? c0 : (q == 1) ? c1
                                        : (q == 2) ? c2 : c3;
                    asm volatile("add.rn.f32x2 %0, %0, %2;\n\t"
                                 "add.rn.f32x2 %1, %1, %3;"
                                 : "+l"(a01), "+l"(a23)
                                 : "l"(vc.x), "l"(vc.y));
                }
            }
        }
    }

    // final fold
    {
        ulonglong2 u; u.x = a01; u.y = a23;
        *(ulonglong2*)(&aggS[wl][o][cg * 4]) = u;
        __syncwarp();
        #pragma unroll
        for (int i = 0; i < 8; i++) {
            const float wv = Wsh[tcur][o][i];
            const float4 a = *(const float4*)(&aggS[wl][i][cg * 4]);
            ax += wv * a.x; ay += wv * a.y; az += wv * a.z; aw += wv * a.w;
        }
    }

    float bias = 0.f;
    #pragma unroll
    for (int t = 0; t < NTYPES; t++) {
        int lo = __shfl_sync(0xffffffffu, myBnd, t);
        int hi = __shfl_sync(0xffffffffu, myBnd, t + 1);
        bias += (float)(hi - lo) * Bsh[t][o];
    }

    float4 res = { ax + bias, ay + bias, az + bias, aw + bias };
    *(float4*)(out + (size_t)n * 128 + o * 16 + cg * 4) = res;
}

// ---------------- launch ----------------

extern "C" void kernel_launch(void* const* d_in, const int* in_sizes, int n_in,
                              void* d_out, int out_size)
{
    const float* x   = (const float*)d_in[0];
    const float* W   = (const float*)d_in[1];
    const float* Bv  = (const float*)d_in[2];
    const int*   src = (const int*)  d_in[3];
    const int*   dst = (const int*)  d_in[4];
    const int*   et  = (const int*)  d_in[5];
    float*       out = (float*)d_out;

    const int E = in_sizes[3];
    const int N = in_sizes[0] / 128;
    const int B = N * NTYPES;

    void* cnt_ptr = nullptr;
    cudaGetSymbolAddress(&cnt_ptr, g_cnt);
    cudaMemsetAsync(cnt_ptr, 0, (size_t)B * sizeof(int));

    const int tb = 256;
    hist_kernel<<<(E + tb - 1) / tb, tb>>>(dst, et, E);

    const int nblk = (B + SCAN_BS - 1) / SCAN_BS;
    scan_pass1<<<nblk, SCAN_BS>>>(B);
    scan_pass2<<<1, SCAN_BS>>>(nblk, B, E);
    scan_pass3<<<nblk, SCAN_BS>>>(B);

    scatter_kernel<<<(E + tb - 1) / tb, tb>>>(src, E);
    gcl_main<<<(N + 7) / 8, 256>>>(x, W, Bv, out, N);
}